// round 13
// baseline (speedup 1.0000x reference)
#include <cuda_runtime.h>
#include <cuda_fp16.h>
#include <math.h>

// Problem constants (from reference): N=50000, E=800000, dims all 128.
#define MAXN 50000
#define MAXE 800000
#define D 128
#define SCAN_BLK 1024
#define MAX_SCAN_BLOCKS 64

// Scratch (no allocations allowed -> __device__ globals).
__device__ __align__(16) uint2  g_semn2[MAXN * 32];  // normalized semantic vecs, fp16 (4/lane)
__device__ __align__(16) float  g_agg[MAXN * D];     // softmax-weighted aggregate per dst
__device__ __align__(16) float  g_Wt[D * D];         // W_src^T: Wt[k*128+j] = W[j*128+k]
__device__ float g_bcoef[MAXN];                      // sum(attn) per dst (~1 or 0)
__device__ int   g_deg[MAXN];
__device__ int   g_offs[MAXN + 1];
__device__ int   g_cursor[MAXN];
__device__ int   g_srcs[MAXE];                       // src ids grouped by dst
__device__ int   g_is64;                             // edge_index dtype flag
__device__ int   g_bsums[MAX_SCAN_BLOCKS];           // per-block sums for scan

// ---- f32x2 packed-math helpers (SASS: FFMA2; only reachable via PTX) ------
__device__ __forceinline__ unsigned long long pk2(float a, float b) {
    unsigned long long r;
    asm("mov.b64 %0, {%1, %2};" : "=l"(r) : "f"(a), "f"(b));
    return r;
}
__device__ __forceinline__ float2 unpk2(unsigned long long v) {
    float2 r;
    asm("mov.b64 {%0, %1}, %2;" : "=f"(r.x), "=f"(r.y) : "l"(v));
    return r;
}
__device__ __forceinline__ void fma2(unsigned long long& d,
                                     unsigned long long a, unsigned long long b) {
    asm("fma.rn.f32x2 %0, %1, %2, %0;" : "+l"(d) : "l"(a), "l"(b));
}

// ---------------------------------------------------------------------------
// K0: fused setup — zero histogram, transpose W, detect edge dtype (block 0),
// and normalize semantic vectors to fp16 (warp per node).
// int64 ids < 50000 => every odd 32-bit word is 0; int32 => essentially never.
// ---------------------------------------------------------------------------
__global__ __launch_bounds__(256) void setup_kernel(const float* __restrict__ W,
                                                    const float* __restrict__ sem,
                                                    const int* __restrict__ p32,
                                                    int n, int e) {
    int i = blockIdx.x * blockDim.x + threadIdx.x;
    if (i < n) g_deg[i] = 0;
    if (i < D * D) {
        int j = i >> 7;      // row of W
        int k = i & 127;     // col of W
        g_Wt[k * D + j] = W[i];
    }
    if (blockIdx.x == 0) {
        __shared__ int nz;
        if (threadIdx.x == 0) nz = 0;
        __syncthreads();
        int idx = 2 * (int)threadIdx.x + 1;          // sample odd words
        if (threadIdx.x < 128 && idx < 2 * e && p32[idx] != 0) atomicAdd(&nz, 1);
        __syncthreads();
        if (threadIdx.x == 0) g_is64 = (nz == 0) ? 1 : 0;
    }
    // normalization: warp per node
    int warp = i >> 5;
    int lane = threadIdx.x & 31;
    if (warp < n) {
        float4 v = ((const float4*)sem)[(size_t)warp * 32 + lane];
        float ss = v.x * v.x + v.y * v.y + v.z * v.z + v.w * v.w;
        #pragma unroll
        for (int o = 16; o; o >>= 1) ss += __shfl_xor_sync(0xffffffffu, ss, o);
        float inv = 1.0f / fmaxf(sqrtf(ss), 1e-8f);
        __half2 h0 = __floats2half2_rn(v.x * inv, v.y * inv);
        __half2 h1 = __floats2half2_rn(v.z * inv, v.w * inv);
        uint2 u;
        u.x = *(const unsigned int*)&h0;
        u.y = *(const unsigned int*)&h1;
        g_semn2[(size_t)warp * 32 + lane] = u;
    }
}

// ---------------------------------------------------------------------------
// K1: degree histogram over dst, 4 edges/thread, vector loads (range-guarded)
// ---------------------------------------------------------------------------
__global__ void hist_kernel(const void* __restrict__ ei, int e, int n) {
    int i = (blockIdx.x * blockDim.x + threadIdx.x) * 4;
    if (i >= e) return;
    int d0 = -1, d1 = -1, d2 = -1, d3 = -1;
    if (i + 4 <= e) {
        if (g_is64) {
            const long long* p = (const long long*)ei + e;
            longlong2 v0 = *(const longlong2*)(p + i);
            longlong2 v1 = *(const longlong2*)(p + i + 2);
            d0 = (int)v0.x; d1 = (int)v0.y; d2 = (int)v1.x; d3 = (int)v1.y;
        } else {
            const int* p = (const int*)ei + e;
            int4 v = *(const int4*)(p + i);
            d0 = v.x; d1 = v.y; d2 = v.z; d3 = v.w;
        }
    } else {
        for (int j = 0; j + i < e; ++j) {
            int d = g_is64 ? (int)((const long long*)ei)[e + i + j]
                           : ((const int*)ei)[e + i + j];
            if (j == 0) d0 = d; else if (j == 1) d1 = d; else d2 = d;
        }
    }
    if ((unsigned)d0 < (unsigned)n) atomicAdd(&g_deg[d0], 1);
    if ((unsigned)d1 < (unsigned)n) atomicAdd(&g_deg[d1], 1);
    if ((unsigned)d2 < (unsigned)n) atomicAdd(&g_deg[d2], 1);
    if ((unsigned)d3 < (unsigned)n) atomicAdd(&g_deg[d3], 1);
}

// ---------------------------------------------------------------------------
// K2a: per-block reduce of degrees -> g_bsums
// ---------------------------------------------------------------------------
__global__ __launch_bounds__(SCAN_BLK) void scan_sum_kernel(int n) {
    __shared__ int wsum[32];
    int i = blockIdx.x * SCAN_BLK + threadIdx.x;
    int v = (i < n) ? g_deg[i] : 0;
    int lane = threadIdx.x & 31, wid = threadIdx.x >> 5;
    int s = v;
    #pragma unroll
    for (int o = 16; o; o >>= 1) s += __shfl_xor_sync(0xffffffffu, s, o);
    if (lane == 0) wsum[wid] = s;
    __syncthreads();
    if (wid == 0) {
        int t = wsum[lane];
        #pragma unroll
        for (int o = 16; o; o >>= 1) t += __shfl_xor_sync(0xffffffffu, t, o);
        if (lane == 0) g_bsums[blockIdx.x] = t;
    }
}

// ---------------------------------------------------------------------------
// K2b: per-block element scan; each block re-scans the (<=64) block sums in
// shared to get its own offset (folds the old middle kernel away).
// ---------------------------------------------------------------------------
__global__ __launch_bounds__(SCAN_BLK) void scan_write_kernel(int n, int nblk) {
    __shared__ int wsum[32];
    __shared__ int bpre[MAX_SCAN_BLOCKS];   // inclusive scan of block sums
    int tid = threadIdx.x;
    if (tid < MAX_SCAN_BLOCKS) bpre[tid] = (tid < nblk) ? g_bsums[tid] : 0;
    __syncthreads();
    #pragma unroll
    for (int o = 1; o < MAX_SCAN_BLOCKS; o <<= 1) {
        int t = (tid < MAX_SCAN_BLOCKS && tid >= o) ? bpre[tid - o] : 0;
        __syncthreads();
        if (tid < MAX_SCAN_BLOCKS) bpre[tid] += t;
        __syncthreads();
    }
    int block_off = (blockIdx.x == 0) ? 0 : bpre[blockIdx.x - 1];

    int i = blockIdx.x * SCAN_BLK + tid;
    int v = (i < n) ? g_deg[i] : 0;
    int lane = tid & 31, wid = tid >> 5;
    int incl = v;
    #pragma unroll
    for (int o = 1; o < 32; o <<= 1) {
        int t = __shfl_up_sync(0xffffffffu, incl, o);
        if (lane >= o) incl += t;
    }
    if (lane == 31) wsum[wid] = incl;
    __syncthreads();
    if (wid == 0) {
        int s = wsum[lane];
        #pragma unroll
        for (int o = 1; o < 32; o <<= 1) {
            int t = __shfl_up_sync(0xffffffffu, s, o);
            if (lane >= o) s += t;
        }
        wsum[lane] = s;
    }
    __syncthreads();
    if (i < n) {
        int excl = (incl - v) + (wid ? wsum[wid - 1] : 0) + block_off;
        g_offs[i] = excl;
        g_cursor[i] = excl;
    }
    if (blockIdx.x == gridDim.x - 1 && tid == 0) g_offs[n] = bpre[nblk - 1];
}

// ---------------------------------------------------------------------------
// K3: counting-sort scatter of src ids grouped by dst, 2 edges/thread
// ---------------------------------------------------------------------------
__global__ void scatter_kernel(const void* __restrict__ ei, int e, int n) {
    int i = (blockIdx.x * blockDim.x + threadIdx.x) * 2;
    if (i >= e) return;
    int s0, s1 = -1, d0, d1 = -1;
    if (g_is64) {
        const longlong2* ps = (const longlong2*)ei;
        const longlong2* pd = (const longlong2*)((const long long*)ei + e);
        longlong2 vs = ps[i >> 1], vd = pd[i >> 1];
        s0 = (int)vs.x; d0 = (int)vd.x;
        if (i + 1 < e) { s1 = (int)vs.y; d1 = (int)vd.y; }
    } else {
        const int2* ps = (const int2*)ei;
        const int2* pd = (const int2*)((const int*)ei + e);
        int2 vs = ps[i >> 1], vd = pd[i >> 1];
        s0 = vs.x; d0 = vd.x;
        if (i + 1 < e) { s1 = vs.y; d1 = vd.y; }
    }
    if ((unsigned)s0 < (unsigned)n && (unsigned)d0 < (unsigned)n)
        g_srcs[atomicAdd(&g_cursor[d0], 1)] = s0;
    if ((unsigned)s1 < (unsigned)n && (unsigned)d1 < (unsigned)n)
        g_srcs[atomicAdd(&g_cursor[d1], 1)] = s1;
}

// ---------------------------------------------------------------------------
// K4: per-dst softmax aggregation (warp per dst). Cosine sim in [-1,1] =>
// exp(sim) is unconditionally safe -> no online max, no branches.
// 4-edge software pipeline: all 8 gathers issued before any compute.
//     agg = (sum_e exp(sim)*x[src]) / (sum_e exp(sim) + 1e-16)
//     bcoef = s / (s + 1e-16)
// ---------------------------------------------------------------------------
__device__ __forceinline__ float semdot(uint2 u, float2 sd0, float2 sd1) {
    float2 a0 = __half22float2(*(const __half2*)&u.x);
    float2 a1 = __half22float2(*(const __half2*)&u.y);
    return sd0.x * a0.x + sd0.y * a0.y + sd1.x * a1.x + sd1.y * a1.y;
}

__global__ __launch_bounds__(256) void agg_kernel(const float* __restrict__ x, int n) {
    int warp = (blockIdx.x * blockDim.x + threadIdx.x) >> 5;
    int lane = threadIdx.x & 31;
    if (warp >= n) return;
    int beg = g_offs[warp];
    int end = g_offs[warp + 1];

    const float4* x4 = (const float4*)x;

    uint2 du = g_semn2[(size_t)warp * 32 + lane];
    float2 sd0 = __half22float2(*(const __half2*)&du.x);
    float2 sd1 = __half22float2(*(const __half2*)&du.y);

    float s = 0.0f;
    float4 acc = make_float4(0.f, 0.f, 0.f, 0.f);

    int i = beg;
    for (; i + 4 <= end; i += 4) {
        int s0 = g_srcs[i], s1 = g_srcs[i + 1], s2 = g_srcs[i + 2], s3 = g_srcs[i + 3];
        // issue all gathers up front (MLP = 8 big loads in flight)
        uint2 u0 = g_semn2[(size_t)s0 * 32 + lane];
        uint2 u1 = g_semn2[(size_t)s1 * 32 + lane];
        uint2 u2 = g_semn2[(size_t)s2 * 32 + lane];
        uint2 u3 = g_semn2[(size_t)s3 * 32 + lane];
        float4 x0 = x4[(size_t)s0 * 32 + lane];
        float4 x1 = x4[(size_t)s1 * 32 + lane];
        float4 x2 = x4[(size_t)s2 * 32 + lane];
        float4 x3 = x4[(size_t)s3 * 32 + lane];

        float p0 = semdot(u0, sd0, sd1);
        float p1 = semdot(u1, sd0, sd1);
        float p2 = semdot(u2, sd0, sd1);
        float p3 = semdot(u3, sd0, sd1);
        #pragma unroll
        for (int o = 16; o; o >>= 1) {
            p0 += __shfl_xor_sync(0xffffffffu, p0, o);
            p1 += __shfl_xor_sync(0xffffffffu, p1, o);
            p2 += __shfl_xor_sync(0xffffffffu, p2, o);
            p3 += __shfl_xor_sync(0xffffffffu, p3, o);
        }
        float w0 = __expf(p0), w1 = __expf(p1), w2 = __expf(p2), w3 = __expf(p3);
        s += (w0 + w1) + (w2 + w3);
        acc.x += w0 * x0.x + w1 * x1.x + w2 * x2.x + w3 * x3.x;
        acc.y += w0 * x0.y + w1 * x1.y + w2 * x2.y + w3 * x3.y;
        acc.z += w0 * x0.z + w1 * x1.z + w2 * x2.z + w3 * x3.z;
        acc.w += w0 * x0.w + w1 * x1.w + w2 * x2.w + w3 * x3.w;
    }
    for (; i < end; ++i) {
        int sA = g_srcs[i];
        uint2 uA = g_semn2[(size_t)sA * 32 + lane];
        float4 xA = x4[(size_t)sA * 32 + lane];
        float p = semdot(uA, sd0, sd1);
        #pragma unroll
        for (int o = 16; o; o >>= 1) p += __shfl_xor_sync(0xffffffffu, p, o);
        float w = __expf(p);
        s += w;
        acc.x += w * xA.x; acc.y += w * xA.y;
        acc.z += w * xA.z; acc.w += w * xA.w;
    }

    float inv = 1.0f / (s + 1e-16f);
    ((float4*)g_agg)[(size_t)warp * 32 + lane] =
        make_float4(acc.x * inv, acc.y * inv, acc.z * inv, acc.w * inv);
    if (lane == 0) g_bcoef[warp] = s * inv;
}

// ---------------------------------------------------------------------------
// K5: out[r] = agg[r] @ W^T + bcoef[r] * b  using packed f32x2 FMA.
// A staged DUPLICATED in shared as (a,a) float2 pairs -> LDS.64 broadcast
// feeds the fma2 multiplicand with zero packing movs. W pairs packed once/k.
// 32 rows/block, 8 warps x 4 rows; lane owns cols lane*4..lane*4+3.
// At the f32x2 issue floor (~24us chip-wide) — only tensor cores beat this.
// ---------------------------------------------------------------------------
#define GR 32
__global__ __launch_bounds__(256) void gemm_kernel(const float* __restrict__ bias,
                                                   float* __restrict__ out, int n) {
    __shared__ float2 shA2[GR * D];   // 32 KB, duplicated pairs
    __shared__ float  shB[D];

    int tid = threadIdx.x;
    int rbase = blockIdx.x * GR;

    if (tid < D) shB[tid] = bias[tid];
    for (int i = tid; i < GR * 32; i += 256) {        // i indexes float4s of A
        int r = rbase + (i >> 5);
        float4 a = (r < n) ? ((const float4*)g_agg)[(size_t)rbase * 32 + i]
                           : make_float4(0.f, 0.f, 0.f, 0.f);
        ((float4*)shA2)[i * 2 + 0] = make_float4(a.x, a.x, a.y, a.y);
        ((float4*)shA2)[i * 2 + 1] = make_float4(a.z, a.z, a.w, a.w);
    }
    __syncthreads();

    int warp = tid >> 5, lane = tid & 31;
    const float4* Wt4 = (const float4*)g_Wt;
    int r0 = warp * 4;

    unsigned long long acc01[4], acc23[4];
    #pragma unroll
    for (int r = 0; r < 4; r++) { acc01[r] = pk2(0.f, 0.f); acc23[r] = pk2(0.f, 0.f); }

    #pragma unroll 8
    for (int k = 0; k < D; ++k) {
        float4 w = __ldg(&Wt4[k * 32 + lane]);
        unsigned long long w01 = pk2(w.x, w.y);
        unsigned long long w23 = pk2(w.z, w.w);
        #pragma unroll
        for (int r = 0; r < 4; r++) {
            unsigned long long a =
                *(const unsigned long long*)&shA2[(r0 + r) * D + k];  // broadcast
            fma2(acc01[r], a, w01);
            fma2(acc23[r], a, w23);
        }
    }

    #pragma unroll
    for (int r = 0; r < 4; r++) {
        int row = rbase + r0 + r;
        if (row >= n) break;
        float bc = g_bcoef[row];
        float2 e01 = unpk2(acc01[r]);
        float2 e23 = unpk2(acc23[r]);
        float4 o;
        o.x = e01.x + bc * shB[lane * 4 + 0];
        o.y = e01.y + bc * shB[lane * 4 + 1];
        o.z = e23.x + bc * shB[lane * 4 + 2];
        o.w = e23.y + bc * shB[lane * 4 + 3];
        ((float4*)out)[(size_t)row * 32 + lane] = o;
    }
}

// ---------------------------------------------------------------------------
// Launch.
// Inputs (metadata order): x[N,128] f32, edge_index[2,E] (int32 or int64),
//   semantic_vec[N,128] f32, W_src[128,128] f32, b_src[128] f32,
//   W_dst (unused), b_dst (unused).
// Output: out[N,128] f32.
// Algebra: out = (sum_e attn*x[src])@W^T + (sum_e attn)*b  -> the E-scale GEMM
// collapses to one N-scale GEMM after aggregation (16x FLOP reduction).
// ---------------------------------------------------------------------------
extern "C" void kernel_launch(void* const* d_in, const int* in_sizes, int n_in,
                              void* d_out, int out_size) {
    const float* x   = (const float*)d_in[0];
    const void*  ei  = d_in[1];
    const float* sem = (const float*)d_in[2];
    const float* W   = (const float*)d_in[3];
    const float* b   = (const float*)d_in[4];
    float*       out = (float*)d_out;

    int n = in_sizes[0] / D;   // 50000
    int e = in_sizes[1] / 2;   // 800000

    int nblk = (n + SCAN_BLK - 1) / SCAN_BLK;   // 49 <= 64

    // setup grid must cover: n warps for norm (n*32 threads), n for deg, D*D for Wt
    {
        long long tot = (long long)n * 32;
        if (tot < n) tot = n;
        if (tot < D * D) tot = D * D;
        int blocks = (int)((tot + 255) / 256);
        setup_kernel<<<blocks, 256>>>(W, sem, (const int*)ei, n, e);
    }
    hist_kernel<<<(e / 4 + 255) / 256, 256>>>(ei, e, n);
    scan_sum_kernel<<<nblk, SCAN_BLK>>>(n);
    scan_write_kernel<<<nblk, SCAN_BLK>>>(n, nblk);
    scatter_kernel<<<(e / 2 + 255) / 256, 256>>>(ei, e, n);
    agg_kernel<<<(n + 7) / 8, 256>>>(x, n);
    gemm_kernel<<<(n + GR - 1) / GR, 256>>>(b, out, n);
}